// round 8
// baseline (speedup 1.0000x reference)
#include <cuda_runtime.h>
#include <math.h>

#define TPB   512
#define NWARP 16
#define TCC   8          // input channels per gather tile
#define GROWS (3 * TCC)  // 24 rows per gather tile
#define GSZ   (GROWS * 128)

typedef unsigned long long ull;

// ---------------- transposed-weight scratch (prep kernels fill these) -------
// Layout: Wt[(c*3 + k)*COUT + o] = W[(o*CIN + c)*3 + k]
__device__ __align__(16) float g_Wt1[128 * 3 * 256];
__device__ __align__(16) float g_Wt2[256 * 3 * 128];
__device__ __align__(16) float g_Wt3[128 * 3 * 64];

// ---------------- f32x2 helpers ---------------------------------------------
__device__ __forceinline__ ull fma2(ull a, ull b, ull c) {
    ull d;
    asm("fma.rn.f32x2 %0, %1, %2, %3;" : "=l"(d) : "l"(a), "l"(b), "l"(c));
    return d;
}
__device__ __forceinline__ ull add2(ull a, ull b) {
    ull d;
    asm("add.rn.f32x2 %0, %1, %2;" : "=l"(d) : "l"(a), "l"(b));
    return d;
}
__device__ __forceinline__ ull dup2(float x) {
    ull d;
    asm("mov.b64 %0, {%1, %1};" : "=l"(d) : "f"(x));
    return d;
}
__device__ __forceinline__ float2 unpack2(ull v) {
    float2 r;
    asm("mov.b64 {%0, %1}, %2;" : "=f"(r.x), "=f"(r.y) : "l"(v));
    return r;
}
__device__ __forceinline__ float wredsum(float v) {
#pragma unroll
    for (int o = 16; o; o >>= 1) v += __shfl_xor_sync(0xffffffffu, v, o);
    return v;
}

// ---------------- weight transpose prep -------------------------------------
template <int CIN, int COUT>
__device__ __forceinline__ void prep_body(const float* __restrict__ W, float* __restrict__ Wt) {
    int i = blockIdx.x * blockDim.x + threadIdx.x;
    if (i < CIN * 3 * COUT) {
        int o  = i % COUT;
        int ck = i / COUT;
        int k  = ck % 3;
        int c  = ck / 3;
        Wt[i] = W[(o * CIN + c) * 3 + k];
    }
}
__global__ void prep1(const float* __restrict__ W) { prep_body<128, 256>(W, g_Wt1); }
__global__ void prep2(const float* __restrict__ W) { prep_body<256, 128>(W, g_Wt2); }
__global__ void prep3(const float* __restrict__ W) { prep_body<128, 64 >(W, g_Wt3); }

// ---------------- gather one c-tile into G (LN+leaky folded in) -------------
// Task (jl, mq): 4 consecutive m's of row jl = 3*c_local + k.
// IDXT[k*128 + m] = indexes[3m + k]  (conflict-free int4 loads).
// G column 127 is exact 0 (pad for acc m=127).
template <bool XF>
__device__ __forceinline__ void gather_tile(const float* __restrict__ sIn,
                                            float* __restrict__ G,
                                            const int* __restrict__ IDXT,
                                            int cb, int tid, float mean, float inv) {
#pragma unroll
    for (int r = 0; r < 2; r++) {
        int e = tid + r * TPB;
        if (e < GROWS * 32) {
            int jl = e >> 5, mq = e & 31, m0 = mq << 2;
            int c = jl / 3, k = jl - 3 * c;
            int4 id = *(const int4*)(IDXT + (k << 7) + m0);
            const float* row = sIn + ((cb + c) << 7);
            float v0 = row[id.x], v1 = row[id.y], v2 = row[id.z];
            if (XF) {
                v0 = (v0 - mean) * inv; v0 = fmaxf(v0, 0.01f * v0);
                v1 = (v1 - mean) * inv; v1 = fmaxf(v1, 0.01f * v1);
                v2 = (v2 - mean) * inv; v2 = fmaxf(v2, 0.01f * v2);
            }
            float v3 = 0.f;
            if (mq != 31) {
                v3 = row[id.w];
                if (XF) { v3 = (v3 - mean) * inv; v3 = fmaxf(v3, 0.01f * v3); }
            }
            *(float4*)(G + (jl << 7) + m0) = make_float4(v0, v1, v2, v3);
        }
    }
}

// ---------------- GEMM accumulate over one tile: OW=16, MI=4 -----------------
// acc[j][mi]: output pair (o=Obase+2j, +1) at m = m0+mi
template <int COUT>
__device__ __forceinline__ void accum_tile(const float* __restrict__ G,
                                           const float* __restrict__ Wt,
                                           int cb, int Obase, int m0,
                                           ull (&acc)[8][4]) {
#pragma unroll 2
    for (int cl = 0; cl < TCC; cl++) {
        const float* gr = G + cl * 384 + m0;
        const float* wb = Wt + (size_t)((cb + cl) * 3) * COUT + Obase;
#pragma unroll
        for (int k = 0; k < 3; k++) {
            float4 g = *(const float4*)(gr + (k << 7));
            ull gd0 = dup2(g.x), gd1 = dup2(g.y), gd2 = dup2(g.z), gd3 = dup2(g.w);
            const ulonglong2* wp = (const ulonglong2*)(wb + k * COUT);
#pragma unroll
            for (int jj = 0; jj < 4; jj++) {
                ulonglong2 wv = wp[jj];
                acc[2*jj][0] = fma2(wv.x, gd0, acc[2*jj][0]);
                acc[2*jj][1] = fma2(wv.x, gd1, acc[2*jj][1]);
                acc[2*jj][2] = fma2(wv.x, gd2, acc[2*jj][2]);
                acc[2*jj][3] = fma2(wv.x, gd3, acc[2*jj][3]);
                acc[2*jj+1][0] = fma2(wv.y, gd0, acc[2*jj+1][0]);
                acc[2*jj+1][1] = fma2(wv.y, gd1, acc[2*jj+1][1]);
                acc[2*jj+1][2] = fma2(wv.y, gd2, acc[2*jj+1][2]);
                acc[2*jj+1][3] = fma2(wv.y, gd3, acc[2*jj+1][3]);
            }
        }
    }
}

// ---------------- pipelined sweep; warp accumulates only tiles [tlo,thi) -----
template <int CIN, int COUT, bool XF>
__device__ __forceinline__ void conv_sweep(const float* __restrict__ sIn,
                                           const float* __restrict__ Wt,
                                           float* __restrict__ G0, float* __restrict__ G1,
                                           const int* __restrict__ IDXT,
                                           int Obase, int m0, int tid, int tlo, int thi,
                                           float xm, float xi, ull (&acc)[8][4]) {
    constexpr int NT = CIN / TCC;
    gather_tile<XF>(sIn, G0, IDXT, 0, tid, xm, xi);
#pragma unroll 1
    for (int t = 0; t < NT; t++) {
        __syncthreads();
        if (t + 1 < NT)
            gather_tile<XF>(sIn, (t & 1) ? G0 : G1, IDXT, (t + 1) * TCC, tid, xm, xi);
        if (t >= tlo && t < thi)
            accum_tile<COUT>((t & 1) ? G1 : G0, Wt, t * TCC, Obase, m0, acc);
    }
    __syncthreads();
}

// ---------------- LN stats finalize ------------------------------------------
__device__ __forceinline__ void ln_stats(float ls1, float ls2,
                                         float* __restrict__ RED, float* __restrict__ STAT,
                                         int tid, int w, int lane, float n) {
    float r1 = wredsum(ls1), r2 = wredsum(ls2);
    if (lane == 0) { RED[w] = r1; RED[NWARP + w] = r2; }
    __syncthreads();
    if (tid == 0) {
        float s1 = 0.f, s2 = 0.f;
#pragma unroll
        for (int i = 0; i < NWARP; i++) { s1 += RED[i]; s2 += RED[NWARP + i]; }
        float mean = s1 / n;
        float var  = fmaxf((s2 - s1 * mean) / (n - 1.0f), 0.f);
        STAT[0] = mean;
        STAT[1] = 1.0f / (sqrtf(var) + 1e-5f);
    }
    __syncthreads();
}

// ---------------- fused per-tree kernel --------------------------------------
#define SMEM_FLOATS (32768 + 16384 + 2 * GSZ + 384 + 2 * NWARP + 64 + 2)
#define SMEM_BYTES  (SMEM_FLOATS * 4)

__global__ void __launch_bounds__(TPB, 1) bao_kernel(
    const float* __restrict__ trees, const int* __restrict__ indexes,
    const float* __restrict__ b1, const float* __restrict__ b2,
    const float* __restrict__ b3,
    const float* __restrict__ W4, const float* __restrict__ b4,
    const float* __restrict__ W5, const float* __restrict__ b5,
    float* __restrict__ out) {
    extern __shared__ float sm[];
    float* S1   = sm;                       // 256x128 L1-out (pre-LN) / partial buffer
    float* S0   = sm + 32768;               // 128x128 trees / L2-out / L3-in
    float* G0   = sm + 49152;
    float* G1   = G0 + GSZ;
    int*   IDXT = (int*)(G1 + GSZ);         // 3 x 128
    float* RED  = (float*)(IDXT + 384);
    float* POOL = RED + 2 * NWARP;
    float* STAT = POOL + 64;

    const int tid = threadIdx.x, w = tid >> 5, lane = tid & 31;
    const int b = blockIdx.x;
    const int m0 = lane << 2;

    // stage tree + transposed indexes
    {
        const float4* tin = (const float4*)(trees + (size_t)b * 16384);
        float4* s0v = (float4*)S0;
        for (int i = tid; i < 4096; i += TPB) s0v[i] = tin[i];
        const int* ip = indexes + (size_t)b * 381;
        if (tid < 384) {
            int k = tid >> 7, m = tid & 127;
            IDXT[tid] = (m < 127) ? ip[3 * m + k] : 0;
        }
    }
    __syncthreads();

    // ================= Layer 1: CIN=128 COUT=256, direct store ===============
    {
        const int Obase = w * 16;
        ull acc[8][4];
#pragma unroll
        for (int j = 0; j < 8; j++)
#pragma unroll
            for (int mi = 0; mi < 4; mi++) acc[j][mi] = 0ull;
        conv_sweep<128, 256, false>(S0, g_Wt1, G0, G1, IDXT, Obase, m0, tid,
                                    0, 16, 0.f, 1.f, acc);
        float ls1 = 0.f, ls2 = 0.f;
#pragma unroll
        for (int j = 0; j < 8; j++) {
            int o0 = Obase + 2 * j;
            float bb0 = b1[o0], bb1 = b1[o0 + 1];
#pragma unroll
            for (int mi = 0; mi < 4; mi++) {
                int m = m0 + mi;
                if (m < 127) {
                    float2 v = unpack2(acc[j][mi]);
                    float x0 = v.x + bb0, x1 = v.y + bb1;
                    S1[o0 * 128 + m + 1]       = x0;
                    S1[(o0 + 1) * 128 + m + 1] = x1;
                    ls1 += x0 + x1;
                    ls2 += x0 * x0 + x1 * x1;
                }
            }
        }
        if (tid < 256) S1[tid * 128] = 0.f;   // zero node column
        ln_stats(ls1, ls2, RED, STAT, tid, w, lane, 256.f * 128.f);
    }
    float m1 = STAT[0], i1 = STAT[1];

    // ================= Layer 2: CIN=256 COUT=128, K-split 2 ==================
    {
        const int kg = w >> 3, og = w & 7;
        const int Obase = og * 16;
        ull acc[8][4];
#pragma unroll
        for (int j = 0; j < 8; j++)
#pragma unroll
            for (int mi = 0; mi < 4; mi++) acc[j][mi] = 0ull;
        conv_sweep<256, 128, true>(S1, g_Wt2, G0, G1, IDXT, Obase, m0, tid,
                                   kg * 16, kg * 16 + 16, m1, i1, acc);
        // store partials into P = S1 (input fully consumed): rows = kg*64 + pair
        ull* P = (ull*)S1;
#pragma unroll
        for (int j = 0; j < 8; j++) {
            ull* prow = P + (size_t)(kg * 64 + og * 8 + j) * 128 + m0;
            ulonglong2 v01; v01.x = acc[j][0]; v01.y = acc[j][1];
            ulonglong2 v23; v23.x = acc[j][2]; v23.y = acc[j][3];
            *(ulonglong2*)(prow)     = v01;
            *(ulonglong2*)(prow + 2) = v23;
        }
        __syncthreads();
        // reduce kg pairs -> S0 (+bias, stats); node = m+1, m==127 -> node 0 = 0
        float ls1 = 0.f, ls2 = 0.f;
        int jp = tid >> 3, mr = (tid & 7) * 16;
        const ull* p0 = P + (size_t)jp * 128 + mr;
        float bb0 = b2[2 * jp], bb1 = b2[2 * jp + 1];
        float* r0 = S0 + (2 * jp) * 128;
        float* r1 = S0 + (2 * jp + 1) * 128;
#pragma unroll
        for (int q = 0; q < 8; q++) {
            ulonglong2 a = *(const ulonglong2*)(p0 + 2 * q);
            ulonglong2 c = *(const ulonglong2*)(p0 + 8192 + 2 * q);
            ull s0 = add2(a.x, c.x), s1 = add2(a.y, c.y);
#pragma unroll
            for (int h = 0; h < 2; h++) {
                int m = mr + 2 * q + h;
                float2 f = unpack2(h ? s1 : s0);
                float x0, x1;
                int node;
                if (m < 127) { x0 = f.x + bb0; x1 = f.y + bb1; node = m + 1; }
                else         { x0 = 0.f;       x1 = 0.f;       node = 0; }
                r0[node] = x0; r1[node] = x1;
                ls1 += x0 + x1;
                ls2 += x0 * x0 + x1 * x1;
            }
        }
        ln_stats(ls1, ls2, RED, STAT, tid, w, lane, 128.f * 128.f);
    }
    float m2 = STAT[0], i2 = STAT[1];

    // ================= Layer 3: CIN=128 COUT=64, K-split 4, pool =============
    {
        const int kg = w >> 2, og = w & 3;
        const int Obase = og * 16;
        ull acc[8][4];
#pragma unroll
        for (int j = 0; j < 8; j++)
#pragma unroll
            for (int mi = 0; mi < 4; mi++) acc[j][mi] = 0ull;
        conv_sweep<128, 64, true>(S0, g_Wt3, G0, G1, IDXT, Obase, m0, tid,
                                  kg * 4, kg * 4 + 4, m2, i2, acc);
        ull* P = (ull*)S1;
#pragma unroll
        for (int j = 0; j < 8; j++) {
            ull* prow = P + (size_t)(kg * 32 + og * 8 + j) * 128 + m0;
            ulonglong2 v01; v01.x = acc[j][0]; v01.y = acc[j][1];
            ulonglong2 v23; v23.x = acc[j][2]; v23.y = acc[j][3];
            *(ulonglong2*)(prow)     = v01;
            *(ulonglong2*)(prow + 2) = v23;
        }
        __syncthreads();
        // reduce 4 kg partials; stats + per-channel max (node0=0 included)
        float ls1 = 0.f, ls2 = 0.f;
        int jp = tid >> 4, mr = (tid & 15) * 8;
        const ull* p0 = P + (size_t)jp * 128 + mr;
        float bb0 = b3[2 * jp], bb1 = b3[2 * jp + 1];
        float t0 = -3.4e38f, t1 = -3.4e38f;
#pragma unroll
        for (int q = 0; q < 4; q++) {
            ulonglong2 a = *(const ulonglong2*)(p0 + 2 * q);
            ulonglong2 c = *(const ulonglong2*)(p0 + 4096 + 2 * q);
            ulonglong2 d = *(const ulonglong2*)(p0 + 8192 + 2 * q);
            ulonglong2 e = *(const ulonglong2*)(p0 + 12288 + 2 * q);
            ull s0 = add2(add2(a.x, c.x), add2(d.x, e.x));
            ull s1 = add2(add2(a.y, c.y), add2(d.y, e.y));
#pragma unroll
            for (int h = 0; h < 2; h++) {
                int m = mr + 2 * q + h;
                float2 f = unpack2(h ? s1 : s0);
                float x0 = (m < 127) ? f.x + bb0 : 0.f;
                float x1 = (m < 127) ? f.y + bb1 : 0.f;
                ls1 += x0 + x1;
                ls2 += x0 * x0 + x1 * x1;
                t0 = fmaxf(t0, x0);
                t1 = fmaxf(t1, x1);
            }
        }
#pragma unroll
        for (int o = 8; o; o >>= 1) {
            t0 = fmaxf(t0, __shfl_xor_sync(0xffffffffu, t0, o));
            t1 = fmaxf(t1, __shfl_xor_sync(0xffffffffu, t1, o));
        }
        if ((lane & 15) == 0) { POOL[2 * jp] = t0; POOL[2 * jp + 1] = t1; }
        ln_stats(ls1, ls2, RED, STAT, tid, w, lane, 64.f * 128.f);
    }

    // ================= head ==================================================
    if (w == 0) {
        float mean = STAT[0], inv = STAT[1];
        float hv = b4[lane];
#pragma unroll 8
        for (int c = 0; c < 64; c++)
            hv += (POOL[c] - mean) * inv * W4[lane * 64 + c];
        hv = hv > 0.f ? hv : 0.01f * hv;
        float val = wredsum(hv * W5[lane]);
        if (lane == 0) out[b] = val + b5[0];
    }
}

extern "C" void kernel_launch(void* const* d_in, const int* in_sizes, int n_in,
                              void* d_out, int out_size) {
    const float* trees = nullptr; const int* indexes = nullptr;
    const float *W1 = nullptr, *b1 = nullptr, *W2 = nullptr, *b2 = nullptr;
    const float *W3 = nullptr, *b3 = nullptr, *W4 = nullptr, *b4 = nullptr;
    const float *W5 = nullptr, *b5 = nullptr;

    for (int i = 0; i < n_in; i++) {
        int s = in_sizes[i];
        const void* p = d_in[i];
        switch (s) {
            case 33554432: trees   = (const float*)p; break;
            case 780288:   indexes = (const int*)p;   break;
            case 98304:    if (!W1) W1 = (const float*)p; else W2 = (const float*)p; break;
            case 256:      b1 = (const float*)p; break;
            case 128:      b2 = (const float*)p; break;
            case 24576:    W3 = (const float*)p; break;
            case 64:       b3 = (const float*)p; break;
            case 2048:     W4 = (const float*)p; break;
            case 32:       if (!b4) b4 = (const float*)p; else W5 = (const float*)p; break;
            case 1:        b5 = (const float*)p; break;
            default: break;
        }
    }

    prep1<<<(128 * 3 * 256 + 255) / 256, 256>>>(W1);
    prep2<<<(256 * 3 * 128 + 255) / 256, 256>>>(W2);
    prep3<<<(128 * 3 * 64  + 255) / 256, 256>>>(W3);

    cudaFuncSetAttribute(bao_kernel, cudaFuncAttributeMaxDynamicSharedMemorySize, SMEM_BYTES);
    bao_kernel<<<2048, TPB, SMEM_BYTES>>>(trees, indexes, b1, b2, b3, W4, b4, W5, b5,
                                          (float*)d_out);
}

// round 9
// speedup vs baseline: 1.3915x; 1.3915x over previous
#include <cuda_runtime.h>
#include <math.h>

#define TPB   512
#define NWARP 16
#define TCC   8          // input channels per gather tile
#define GROWS (3 * TCC)  // 24 rows per gather tile
#define GSZ   (GROWS * 128)

typedef unsigned long long ull;

// ---------------- transposed-weight scratch (prep kernels fill these) -------
// Layout: Wt[(c*3 + k)*COUT + o] = W[(o*CIN + c)*3 + k]
__device__ __align__(16) float g_Wt1[128 * 3 * 256];
__device__ __align__(16) float g_Wt2[256 * 3 * 128];
__device__ __align__(16) float g_Wt3[128 * 3 * 64];

// ---------------- f32x2 helpers ---------------------------------------------
__device__ __forceinline__ ull fma2(ull a, ull b, ull c) {
    ull d;
    asm("fma.rn.f32x2 %0, %1, %2, %3;" : "=l"(d) : "l"(a), "l"(b), "l"(c));
    return d;
}
__device__ __forceinline__ ull dup2(float x) {
    ull d;
    asm("mov.b64 %0, {%1, %1};" : "=l"(d) : "f"(x));
    return d;
}
__device__ __forceinline__ float2 unpack2(ull v) {
    float2 r;
    asm("mov.b64 {%0, %1}, %2;" : "=f"(r.x), "=f"(r.y) : "l"(v));
    return r;
}
__device__ __forceinline__ float wredsum(float v) {
#pragma unroll
    for (int o = 16; o; o >>= 1) v += __shfl_xor_sync(0xffffffffu, v, o);
    return v;
}
__device__ __forceinline__ float wredmax(float v) {
#pragma unroll
    for (int o = 16; o; o >>= 1) v = fmaxf(v, __shfl_xor_sync(0xffffffffu, v, o));
    return v;
}

// ---------------- weight transpose prep -------------------------------------
template <int CIN, int COUT>
__device__ __forceinline__ void prep_body(const float* __restrict__ W, float* __restrict__ Wt) {
    int i = blockIdx.x * blockDim.x + threadIdx.x;
    if (i < CIN * 3 * COUT) {
        int o  = i % COUT;
        int ck = i / COUT;
        int k  = ck % 3;
        int c  = ck / 3;
        Wt[i] = W[(o * CIN + c) * 3 + k];
    }
}
__global__ void prep1(const float* __restrict__ W) { prep_body<128, 256>(W, g_Wt1); }
__global__ void prep2(const float* __restrict__ W) { prep_body<256, 128>(W, g_Wt2); }
__global__ void prep3(const float* __restrict__ W) { prep_body<128, 64 >(W, g_Wt3); }

// ---------------- gather one c-tile into G (LN+leaky folded in) -------------
// Task (jl, mq): 4 consecutive m's of row jl = 3*c_local + k.
// IDXT[k*128 + m] = indexes[3m + k]  (conflict-free int4 loads).
// G column 127 is exact 0 (pad so float4 loads at m0=124 are harmless).
template <bool XF>
__device__ __forceinline__ void gather_tile(const float* __restrict__ sIn,
                                            float* __restrict__ G,
                                            const int* __restrict__ IDXT,
                                            int cb, int tid, float mean, float inv) {
#pragma unroll
    for (int r = 0; r < 2; r++) {
        int e = tid + r * TPB;
        if (e < GROWS * 32) {
            int jl = e >> 5, mq = e & 31, m0 = mq << 2;
            int c = jl / 3, k = jl - 3 * c;
            int4 id = *(const int4*)(IDXT + (k << 7) + m0);
            const float* row = sIn + ((cb + c) << 7);
            float v0 = row[id.x], v1 = row[id.y], v2 = row[id.z];
            if (XF) {
                v0 = (v0 - mean) * inv; v0 = fmaxf(v0, 0.01f * v0);
                v1 = (v1 - mean) * inv; v1 = fmaxf(v1, 0.01f * v1);
                v2 = (v2 - mean) * inv; v2 = fmaxf(v2, 0.01f * v2);
            }
            float v3 = 0.f;
            if (mq != 31) {
                v3 = row[id.w];
                if (XF) { v3 = (v3 - mean) * inv; v3 = fmaxf(v3, 0.01f * v3); }
            }
            *(float4*)(G + (jl << 7) + m0) = make_float4(v0, v1, v2, v3);
        }
    }
}

// ---------------- GEMM accumulate over one tile ------------------------------
// acc[j][mi]: output pair (o=Obase+2j, +1) at m = m0+mi
template <int COUT, int OW>
__device__ __forceinline__ void accum_tile(const float* __restrict__ G,
                                           const float* __restrict__ Wt,
                                           int cb, int Obase, int m0,
                                           ull (&acc)[OW / 2][4]) {
#pragma unroll 2
    for (int cl = 0; cl < TCC; cl++) {
        const float* gr = G + cl * 384 + m0;
        const float* wb = Wt + (size_t)((cb + cl) * 3) * COUT + Obase;
#pragma unroll
        for (int k = 0; k < 3; k++) {
            float4 g = *(const float4*)(gr + (k << 7));
            ull gd0 = dup2(g.x), gd1 = dup2(g.y), gd2 = dup2(g.z), gd3 = dup2(g.w);
            const ulonglong2* wp = (const ulonglong2*)(wb + k * COUT);
#pragma unroll
            for (int jj = 0; jj < OW / 4; jj++) {
                ulonglong2 wv = wp[jj];
                acc[2*jj][0] = fma2(wv.x, gd0, acc[2*jj][0]);
                acc[2*jj][1] = fma2(wv.x, gd1, acc[2*jj][1]);
                acc[2*jj][2] = fma2(wv.x, gd2, acc[2*jj][2]);
                acc[2*jj][3] = fma2(wv.x, gd3, acc[2*jj][3]);
                acc[2*jj+1][0] = fma2(wv.y, gd0, acc[2*jj+1][0]);
                acc[2*jj+1][1] = fma2(wv.y, gd1, acc[2*jj+1][1]);
                acc[2*jj+1][2] = fma2(wv.y, gd2, acc[2*jj+1][2]);
                acc[2*jj+1][3] = fma2(wv.y, gd3, acc[2*jj+1][3]);
            }
        }
    }
}

// ---------------- pipelined sweep: every warp accumulates every tile ---------
template <int CIN, int COUT, int OW, bool XF>
__device__ __forceinline__ void conv_sweep(const float* __restrict__ sIn,
                                           const float* __restrict__ Wt,
                                           float* __restrict__ G0, float* __restrict__ G1,
                                           const int* __restrict__ IDXT,
                                           int Obase, int m0, int tid,
                                           float xm, float xi, ull (&acc)[OW / 2][4]) {
    constexpr int NT = CIN / TCC;
    gather_tile<XF>(sIn, G0, IDXT, 0, tid, xm, xi);
#pragma unroll 1
    for (int t = 0; t < NT; t++) {
        __syncthreads();
        if (t + 1 < NT)
            gather_tile<XF>(sIn, (t & 1) ? G0 : G1, IDXT, (t + 1) * TCC, tid, xm, xi);
        accum_tile<COUT, OW>((t & 1) ? G1 : G0, Wt, t * TCC, Obase, m0, acc);
    }
    __syncthreads();
}

// ---------------- LN stats finalize ------------------------------------------
__device__ __forceinline__ void ln_stats(float ls1, float ls2,
                                         float* __restrict__ RED, float* __restrict__ STAT,
                                         int tid, int w, int lane, float n) {
    float r1 = wredsum(ls1), r2 = wredsum(ls2);
    if (lane == 0) { RED[w] = r1; RED[NWARP + w] = r2; }
    __syncthreads();
    if (tid == 0) {
        float s1 = 0.f, s2 = 0.f;
#pragma unroll
        for (int i = 0; i < NWARP; i++) { s1 += RED[i]; s2 += RED[NWARP + i]; }
        float mean = s1 / n;
        float var  = fmaxf((s2 - s1 * mean) / (n - 1.0f), 0.f);
        STAT[0] = mean;
        STAT[1] = 1.0f / (sqrtf(var) + 1e-5f);
    }
    __syncthreads();
}

// ---------------- fused per-tree kernel --------------------------------------
#define SMEM_FLOATS (32768 + 16384 + 2 * GSZ + 384 + 2 * NWARP + 64 + 2)
#define SMEM_BYTES  (SMEM_FLOATS * 4)

__global__ void __launch_bounds__(TPB, 1) bao_kernel(
    const float* __restrict__ trees, const int* __restrict__ indexes,
    const float* __restrict__ b1, const float* __restrict__ b2,
    const float* __restrict__ b3,
    const float* __restrict__ W4, const float* __restrict__ b4,
    const float* __restrict__ W5, const float* __restrict__ b5,
    float* __restrict__ out) {
    extern __shared__ float sm[];
    float* S1   = sm;                       // 256x128 L1-out (pre-LN)
    float* S0   = sm + 32768;               // 128x128 trees / L2-out / L3-in
    float* G0   = sm + 49152;
    float* G1   = G0 + GSZ;
    int*   IDXT = (int*)(G1 + GSZ);         // 3 x 128
    float* RED  = (float*)(IDXT + 384);
    float* POOL = RED + 2 * NWARP;
    float* STAT = POOL + 64;

    const int tid = threadIdx.x, w = tid >> 5, lane = tid & 31;
    const int b = blockIdx.x;
    const int m0 = lane << 2;

    // stage tree + transposed indexes
    {
        const float4* tin = (const float4*)(trees + (size_t)b * 16384);
        float4* s0v = (float4*)S0;
        for (int i = tid; i < 4096; i += TPB) s0v[i] = tin[i];
        const int* ip = indexes + (size_t)b * 381;
        if (tid < 384) {
            int k = tid >> 7, m = tid & 127;
            IDXT[tid] = (m < 127) ? ip[3 * m + k] : 0;
        }
    }
    __syncthreads();

    // ================= Layer 1: CIN=128 COUT=256, OW=16, one sweep ===========
    {
        const int Obase = w * 16;
        ull acc[8][4];
#pragma unroll
        for (int j = 0; j < 8; j++)
#pragma unroll
            for (int mi = 0; mi < 4; mi++) acc[j][mi] = 0ull;
        conv_sweep<128, 256, 16, false>(S0, g_Wt1, G0, G1, IDXT, Obase, m0, tid,
                                        0.f, 1.f, acc);
        float ls1 = 0.f, ls2 = 0.f;
#pragma unroll
        for (int j = 0; j < 8; j++) {
            int o0 = Obase + 2 * j;
            float bb0 = b1[o0], bb1 = b1[o0 + 1];
#pragma unroll
            for (int mi = 0; mi < 4; mi++) {
                int m = m0 + mi;
                if (m < 127) {
                    float2 v = unpack2(acc[j][mi]);
                    float x0 = v.x + bb0, x1 = v.y + bb1;
                    S1[o0 * 128 + m + 1]       = x0;
                    S1[(o0 + 1) * 128 + m + 1] = x1;
                    ls1 += x0 + x1;
                    ls2 += x0 * x0 + x1 * x1;
                }
            }
        }
        if (tid < 256) S1[tid * 128] = 0.f;   // zero node column
        ln_stats(ls1, ls2, RED, STAT, tid, w, lane, 256.f * 128.f);
    }
    float m1 = STAT[0], i1 = STAT[1];

    // ================= Layer 2: CIN=256 COUT=128, OW=8, all warps ============
    {
        const int Obase = w * 8;
        ull acc[4][4];
#pragma unroll
        for (int j = 0; j < 4; j++)
#pragma unroll
            for (int mi = 0; mi < 4; mi++) acc[j][mi] = 0ull;
        conv_sweep<256, 128, 8, true>(S1, g_Wt2, G0, G1, IDXT, Obase, m0, tid,
                                      m1, i1, acc);
        float ls1 = 0.f, ls2 = 0.f;
#pragma unroll
        for (int j = 0; j < 4; j++) {
            int o0 = Obase + 2 * j;
            float bb0 = b2[o0], bb1 = b2[o0 + 1];
#pragma unroll
            for (int mi = 0; mi < 4; mi++) {
                int m = m0 + mi;
                if (m < 127) {
                    float2 v = unpack2(acc[j][mi]);
                    float x0 = v.x + bb0, x1 = v.y + bb1;
                    S0[o0 * 128 + m + 1]       = x0;
                    S0[(o0 + 1) * 128 + m + 1] = x1;
                    ls1 += x0 + x1;
                    ls2 += x0 * x0 + x1 * x1;
                }
            }
        }
        if (tid < 128) S0[tid * 128] = 0.f;
        ln_stats(ls1, ls2, RED, STAT, tid, w, lane, 128.f * 128.f);
    }
    float m2 = STAT[0], i2 = STAT[1];

    // ================= Layer 3: CIN=128 COUT=64, OW=4, all warps, pool =======
    {
        const int Obase = w * 4;
        ull acc[2][4];
#pragma unroll
        for (int j = 0; j < 2; j++)
#pragma unroll
            for (int mi = 0; mi < 4; mi++) acc[j][mi] = 0ull;
        conv_sweep<128, 64, 4, true>(S0, g_Wt3, G0, G1, IDXT, Obase, m0, tid,
                                     m2, i2, acc);
        float ls1 = 0.f, ls2 = 0.f;
        float omax[4];
#pragma unroll
        for (int j = 0; j < 2; j++) {
            int o0 = Obase + 2 * j;
            float bb0 = b3[o0], bb1 = b3[o0 + 1];
            float t0 = -3.4e38f, t1 = -3.4e38f;
#pragma unroll
            for (int mi = 0; mi < 4; mi++) {
                if (m0 + mi < 127) {
                    float2 v = unpack2(acc[j][mi]);
                    float x0 = v.x + bb0, x1 = v.y + bb1;
                    ls1 += x0 + x1;
                    ls2 += x0 * x0 + x1 * x1;
                    t0 = fmaxf(t0, x0);
                    t1 = fmaxf(t1, x1);
                }
            }
            omax[2 * j] = t0; omax[2 * j + 1] = t1;
        }
#pragma unroll
        for (int j = 0; j < 4; j++) {
            float mx = wredmax(omax[j]);
            if (lane == 0) POOL[Obase + j] = fmaxf(mx, 0.f);  // zero column joins max
        }
        ln_stats(ls1, ls2, RED, STAT, tid, w, lane, 64.f * 128.f);
    }

    // ================= head ==================================================
    if (w == 0) {
        float mean = STAT[0], inv = STAT[1];
        float hv = b4[lane];
#pragma unroll 8
        for (int c = 0; c < 64; c++)
            hv += (POOL[c] - mean) * inv * W4[lane * 64 + c];
        hv = hv > 0.f ? hv : 0.01f * hv;
        float val = wredsum(hv * W5[lane]);
        if (lane == 0) out[b] = val + b5[0];
    }
}

extern "C" void kernel_launch(void* const* d_in, const int* in_sizes, int n_in,
                              void* d_out, int out_size) {
    const float* trees = nullptr; const int* indexes = nullptr;
    const float *W1 = nullptr, *b1 = nullptr, *W2 = nullptr, *b2 = nullptr;
    const float *W3 = nullptr, *b3 = nullptr, *W4 = nullptr, *b4 = nullptr;
    const float *W5 = nullptr, *b5 = nullptr;

    for (int i = 0; i < n_in; i++) {
        int s = in_sizes[i];
        const void* p = d_in[i];
        switch (s) {
            case 33554432: trees   = (const float*)p; break;
            case 780288:   indexes = (const int*)p;   break;
            case 98304:    if (!W1) W1 = (const float*)p; else W2 = (const float*)p; break;
            case 256:      b1 = (const float*)p; break;
            case 128:      b2 = (const float*)p; break;
            case 24576:    W3 = (const float*)p; break;
            case 64:       b3 = (const float*)p; break;
            case 2048:     W4 = (const float*)p; break;
            case 32:       if (!b4) b4 = (const float*)p; else W5 = (const float*)p; break;
            case 1:        b5 = (const float*)p; break;
            default: break;
        }
    }

    prep1<<<(128 * 3 * 256 + 255) / 256, 256>>>(W1);
    prep2<<<(256 * 3 * 128 + 255) / 256, 256>>>(W2);
    prep3<<<(128 * 3 * 64  + 255) / 256, 256>>>(W3);

    cudaFuncSetAttribute(bao_kernel, cudaFuncAttributeMaxDynamicSharedMemorySize, SMEM_BYTES);
    bao_kernel<<<2048, TPB, SMEM_BYTES>>>(trees, indexes, b1, b2, b3, W4, b4, W5, b5,
                                          (float*)d_out);
}

// round 11
// speedup vs baseline: 1.6727x; 1.2020x over previous
#include <cuda_runtime.h>
#include <math.h>

#define TPB   512
#define NWARP 16

typedef unsigned long long ull;

// ---------------- transposed-weight scratch (prep kernels fill these) -------
// Layout: Wt[(c*3 + k)*COUT + o] = W[(o*CIN + c)*3 + k]
__device__ __align__(16) float g_Wt1[128 * 3 * 256];
__device__ __align__(16) float g_Wt2[256 * 3 * 128];
__device__ __align__(16) float g_Wt3[128 * 3 * 64];

// ---------------- f32x2 helpers ---------------------------------------------
__device__ __forceinline__ ull fma2(ull a, ull b, ull c) {
    ull d;
    asm("fma.rn.f32x2 %0, %1, %2, %3;" : "=l"(d) : "l"(a), "l"(b), "l"(c));
    return d;
}
__device__ __forceinline__ ull dup2(float x) {
    ull d;
    asm("mov.b64 %0, {%1, %1};" : "=l"(d) : "f"(x));
    return d;
}
__device__ __forceinline__ float2 unpack2(ull v) {
    float2 r;
    asm("mov.b64 {%0, %1}, %2;" : "=f"(r.x), "=f"(r.y) : "l"(v));
    return r;
}
__device__ __forceinline__ float wredsum(float v) {
#pragma unroll
    for (int o = 16; o; o >>= 1) v += __shfl_xor_sync(0xffffffffu, v, o);
    return v;
}
__device__ __forceinline__ float wredmax(float v) {
#pragma unroll
    for (int o = 16; o; o >>= 1) v = fmaxf(v, __shfl_xor_sync(0xffffffffu, v, o));
    return v;
}

// ---------------- weight transpose prep -------------------------------------
template <int CIN, int COUT>
__device__ __forceinline__ void prep_body(const float* __restrict__ W, float* __restrict__ Wt) {
    int i = blockIdx.x * blockDim.x + threadIdx.x;
    if (i < CIN * 3 * COUT) {
        int o  = i % COUT;
        int ck = i / COUT;
        int k  = ck % 3;
        int c  = ck / 3;
        Wt[i] = W[(o * CIN + c) * 3 + k];
    }
}
__global__ void prep1(const float* __restrict__ W) { prep_body<128, 256>(W, g_Wt1); }
__global__ void prep2(const float* __restrict__ W) { prep_body<256, 128>(W, g_Wt2); }
__global__ void prep3(const float* __restrict__ W) { prep_body<128, 64 >(W, g_Wt3); }

// ---------------- per-thread gather context (loop-invariant) -----------------
// Thread handles row jl = 3*c + k (c = channel-in-tile, k = kernel tap),
// m-quad mq: 4 consecutive conv positions. Same mapping for every tile and
// every layer; TCC only bounds which threads are active (jl < 3*TCC).
struct GC {
    int4 id;    // gather node indices for the 4 m's (idx of m=127 slot = 0)
    int  goff;  // jl*128 + mq*4  (G write offset, float4-aligned)
    int  c7;    // c * 128
    int  jl;
};

// ---------------- gather one c-tile into G (LN+leaky folded in) -------------
template <bool XF, int TCC>
__device__ __forceinline__ void gather_t(const float* __restrict__ sIn,
                                         float* __restrict__ G, const GC& gc,
                                         int cb, float mean, float inv) {
    if (gc.jl < 3 * TCC) {
        const float* row = sIn + gc.c7 + (cb << 7);
        float v0 = row[gc.id.x], v1 = row[gc.id.y];
        float v2 = row[gc.id.z], v3 = row[gc.id.w];
        if (XF) {
            v0 = (v0 - mean) * inv; v0 = fmaxf(v0, 0.01f * v0);
            v1 = (v1 - mean) * inv; v1 = fmaxf(v1, 0.01f * v1);
            v2 = (v2 - mean) * inv; v2 = fmaxf(v2, 0.01f * v2);
            v3 = (v3 - mean) * inv; v3 = fmaxf(v3, 0.01f * v3);
        }
        // m=127 lane stores a junk-but-finite value; no consumer reads it.
        *(float4*)(G + gc.goff) = make_float4(v0, v1, v2, v3);
    }
}

// ---------------- stage one weight tile into SMEM (coalesced) ----------------
// cb = tile index; each tile is 3*TCC*COUT floats = 3*TCC*COUT/4 float4s.
template <int COUT, int TCC>
__device__ __forceinline__ void stage_w(const float* __restrict__ Wt,
                                        float* __restrict__ WS, int cb, int tid) {
    constexpr int N4 = 3 * TCC * COUT / 4;
    if (tid < N4)
        ((float4*)WS)[tid] = ((const float4*)Wt)[cb * N4 + tid];
}

// ---------------- GEMM accumulate over one tile (W from SMEM) ----------------
template <int COUT, int OW, int TCC>
__device__ __forceinline__ void accum(const float* __restrict__ G,
                                      const float* __restrict__ WS,
                                      int Obase, int m0, ull (&acc)[OW / 2][4]) {
#pragma unroll
    for (int jl = 0; jl < 3 * TCC; jl++) {
        float4 g = *(const float4*)(G + (jl << 7) + m0);
        ull gd0 = dup2(g.x), gd1 = dup2(g.y), gd2 = dup2(g.z), gd3 = dup2(g.w);
        const ulonglong2* wp = (const ulonglong2*)(WS + jl * COUT + Obase);
#pragma unroll
        for (int jj = 0; jj < OW / 4; jj++) {
            ulonglong2 wv = wp[jj];
            acc[2*jj][0] = fma2(wv.x, gd0, acc[2*jj][0]);
            acc[2*jj][1] = fma2(wv.x, gd1, acc[2*jj][1]);
            acc[2*jj][2] = fma2(wv.x, gd2, acc[2*jj][2]);
            acc[2*jj][3] = fma2(wv.x, gd3, acc[2*jj][3]);
            acc[2*jj+1][0] = fma2(wv.y, gd0, acc[2*jj+1][0]);
            acc[2*jj+1][1] = fma2(wv.y, gd1, acc[2*jj+1][1]);
            acc[2*jj+1][2] = fma2(wv.y, gd2, acc[2*jj+1][2]);
            acc[2*jj+1][3] = fma2(wv.y, gd3, acc[2*jj+1][3]);
        }
    }
}

// ---------------- pipelined sweep: stage W+G for t+1 while computing t -------
template <int CIN, int COUT, int OW, int TCC, bool XF>
__device__ __forceinline__ void conv_sweep(const float* __restrict__ sIn,
                                           const float* __restrict__ Wt,
                                           float* __restrict__ G0, float* __restrict__ G1,
                                           float* __restrict__ W0, float* __restrict__ W1,
                                           const GC& gc, int Obase, int m0, int tid,
                                           float xm, float xi, ull (&acc)[OW / 2][4]) {
    constexpr int NT = CIN / TCC;
    stage_w<COUT, TCC>(Wt, W0, 0, tid);
    gather_t<XF, TCC>(sIn, G0, gc, 0, xm, xi);
#pragma unroll 1
    for (int t = 0; t < NT; t++) {
        __syncthreads();
        if (t + 1 < NT) {
            stage_w<COUT, TCC>(Wt, (t & 1) ? W0 : W1, t + 1, tid);
            gather_t<XF, TCC>(sIn, (t & 1) ? G0 : G1, gc, (t + 1) * TCC, xm, xi);
        }
        accum<COUT, OW, TCC>((t & 1) ? G1 : G0, (t & 1) ? W1 : W0, Obase, m0, acc);
    }
    __syncthreads();
}

// ---------------- LN stats finalize ------------------------------------------
__device__ __forceinline__ void ln_stats(float ls1, float ls2,
                                         float* __restrict__ RED, float* __restrict__ STAT,
                                         int tid, int w, int lane, float n) {
    float r1 = wredsum(ls1), r2 = wredsum(ls2);
    if (lane == 0) { RED[w] = r1; RED[NWARP + w] = r2; }
    __syncthreads();
    if (tid == 0) {
        float s1 = 0.f, s2 = 0.f;
#pragma unroll
        for (int i = 0; i < NWARP; i++) { s1 += RED[i]; s2 += RED[NWARP + i]; }
        float mean = s1 / n;
        float var  = fmaxf((s2 - s1 * mean) / (n - 1.0f), 0.f);
        STAT[0] = mean;
        STAT[1] = 1.0f / (sqrtf(var) + 1e-5f);
    }
    __syncthreads();
}

// ---------------- fused per-tree kernel --------------------------------------
// smem: S1 32768 + S0 16384 + 2*1536 G + 2*1536 W + 384 IDXT + 32 + 64 + 2
#define SMEM_FLOATS (32768 + 16384 + 2 * 1536 + 2 * 1536 + 384 + 2 * NWARP + 64 + 2)
#define SMEM_BYTES  (SMEM_FLOATS * 4)

__global__ void __launch_bounds__(TPB, 1) bao_kernel(
    const float* __restrict__ trees, const int* __restrict__ indexes,
    const float* __restrict__ b1, const float* __restrict__ b2,
    const float* __restrict__ b3,
    const float* __restrict__ W4, const float* __restrict__ b4,
    const float* __restrict__ W5, const float* __restrict__ b5,
    float* __restrict__ out) {
    extern __shared__ float sm[];
    float* S1   = sm;                       // 256x128 L1-out (pre-LN)
    float* S0   = sm + 32768;               // 128x128 trees / L2-out / L3-in
    float* G0   = sm + 49152;               // gather bufs (12 x 128 max)
    float* G1   = G0 + 1536;
    float* W0   = G1 + 1536;                // weight-tile bufs (1536 floats max)
    float* W1   = W0 + 1536;
    int*   IDXT = (int*)(W1 + 1536);        // 3 x 128
    float* RED  = (float*)(IDXT + 384);
    float* POOL = RED + 2 * NWARP;
    float* STAT = POOL + 64;

    const int tid = threadIdx.x, w = tid >> 5, lane = tid & 31;
    const int b = blockIdx.x;
    const int m0 = lane << 2;

    // stage tree + transposed indexes
    {
        const float4* tin = (const float4*)(trees + (size_t)b * 16384);
        float4* s0v = (float4*)S0;
        for (int i = tid; i < 4096; i += TPB) s0v[i] = tin[i];
        const int* ip = indexes + (size_t)b * 381;
        if (tid < 384) {
            int k = tid >> 7, m = tid & 127;
            IDXT[tid] = (m < 127) ? ip[3 * m + k] : 0;
        }
    }
    __syncthreads();

    // build per-thread gather context (constant for whole tree)
    GC gc;
    {
        int jl = tid >> 5, mq = tid & 31;
        gc.jl = jl;
        int c = jl / 3;
        gc.c7 = c << 7;
        int k = jl - 3 * c;
        gc.goff = (jl << 7) + (mq << 2);
        gc.id = (jl < 12) ? *(const int4*)(IDXT + (k << 7) + (mq << 2))
                          : make_int4(0, 0, 0, 0);
    }

    // ================= Layer 1: CIN=128 COUT=256, OW=16, TCC=2 ===============
    {
        const int Obase = w * 16;
        ull acc[8][4];
#pragma unroll
        for (int j = 0; j < 8; j++)
#pragma unroll
            for (int mi = 0; mi < 4; mi++) acc[j][mi] = 0ull;
        conv_sweep<128, 256, 16, 2, false>(S0, g_Wt1, G0, G1, W0, W1, gc,
                                           Obase, m0, tid, 0.f, 1.f, acc);
        float ls1 = 0.f, ls2 = 0.f;
#pragma unroll
        for (int j = 0; j < 8; j++) {
            int o0 = Obase + 2 * j;
            float bb0 = b1[o0], bb1 = b1[o0 + 1];
#pragma unroll
            for (int mi = 0; mi < 4; mi++) {
                int m = m0 + mi;
                if (m < 127) {
                    float2 v = unpack2(acc[j][mi]);
                    float x0 = v.x + bb0, x1 = v.y + bb1;
                    S1[o0 * 128 + m + 1]       = x0;
                    S1[(o0 + 1) * 128 + m + 1] = x1;
                    ls1 += x0 + x1;
                    ls2 += x0 * x0 + x1 * x1;
                }
            }
        }
        if (tid < 256) S1[tid * 128] = 0.f;   // zero node column
        ln_stats(ls1, ls2, RED, STAT, tid, w, lane, 256.f * 128.f);
    }
    float m1 = STAT[0], i1 = STAT[1];

    // ================= Layer 2: CIN=256 COUT=128, OW=8, TCC=4 ================
    {
        const int Obase = w * 8;
        ull acc[4][4];
#pragma unroll
        for (int j = 0; j < 4; j++)
#pragma unroll
            for (int mi = 0; mi < 4; mi++) acc[j][mi] = 0ull;
        conv_sweep<256, 128, 8, 4, true>(S1, g_Wt2, G0, G1, W0, W1, gc,
                                         Obase, m0, tid, m1, i1, acc);
        float ls1 = 0.f, ls2 = 0.f;
#pragma unroll
        for (int j = 0; j < 4; j++) {
            int o0 = Obase + 2 * j;
            float bb0 = b2[o0], bb1 = b2[o0 + 1];
#pragma unroll
            for (int mi = 0; mi < 4; mi++) {
                int m = m0 + mi;
                if (m < 127) {
                    float2 v = unpack2(acc[j][mi]);
                    float x0 = v.x + bb0, x1 = v.y + bb1;
                    S0[o0 * 128 + m + 1]       = x0;
                    S0[(o0 + 1) * 128 + m + 1] = x1;
                    ls1 += x0 + x1;
                    ls2 += x0 * x0 + x1 * x1;
                }
            }
        }
        if (tid < 128) S0[tid * 128] = 0.f;
        ln_stats(ls1, ls2, RED, STAT, tid, w, lane, 128.f * 128.f);
    }
    float m2 = STAT[0], i2 = STAT[1];

    // ================= Layer 3: CIN=128 COUT=64, OW=4, TCC=4, pool ===========
    {
        const int Obase = w * 4;
        ull acc[2][4];
#pragma unroll
        for (int j = 0; j < 2; j++)
#pragma unroll
            for (int mi = 0; mi < 4; mi++) acc[j][mi] = 0ull;
        conv_sweep<128, 64, 4, 4, true>(S0, g_Wt3, G0, G1, W0, W1, gc,
                                        Obase, m0, tid, m2, i2, acc);
        float ls1 = 0.f, ls2 = 0.f;
        float omax[4];
#pragma unroll
        for (int j = 0; j < 2; j++) {
            int o0 = Obase + 2 * j;
            float bb0 = b3[o0], bb1 = b3[o0 + 1];
            float t0 = -3.4e38f, t1 = -3.4e38f;
#pragma unroll
            for (int mi = 0; mi < 4; mi++) {
                if (m0 + mi < 127) {
                    float2 v = unpack2(acc[j][mi]);
                    float x0 = v.x + bb0, x1 = v.y + bb1;
                    ls1 += x0 + x1;
                    ls2 += x0 * x0 + x1 * x1;
                    t0 = fmaxf(t0, x0);
                    t1 = fmaxf(t1, x1);
                }
            }
            omax[2 * j] = t0; omax[2 * j + 1] = t1;
        }
#pragma unroll
        for (int j = 0; j < 4; j++) {
            float mx = wredmax(omax[j]);
            if (lane == 0) POOL[Obase + j] = fmaxf(mx, 0.f);  // zero node joins max
        }
        ln_stats(ls1, ls2, RED, STAT, tid, w, lane, 64.f * 128.f);
    }

    // ================= head ==================================================
    if (w == 0) {
        float mean = STAT[0], inv = STAT[1];
        float hv = b4[lane];
#pragma unroll 8
        for (int c = 0; c < 64; c++)
            hv += (POOL[c] - mean) * inv * W4[lane * 64 + c];
        hv = hv > 0.f ? hv : 0.01f * hv;
        float val = wredsum(hv * W5[lane]);
        if (lane == 0) out[b] = val + b5[0];
    }
}

extern "C" void kernel_launch(void* const* d_in, const int* in_sizes, int n_in,
                              void* d_out, int out_size) {
    const float* trees = nullptr; const int* indexes = nullptr;
    const float *W1 = nullptr, *b1 = nullptr, *W2 = nullptr, *b2 = nullptr;
    const float *W3 = nullptr, *b3 = nullptr, *W4 = nullptr, *b4 = nullptr;
    const float *W5 = nullptr, *b5 = nullptr;

    for (int i = 0; i < n_in; i++) {
        int s = in_sizes[i];
        const void* p = d_in[i];
        switch (s) {
            case 33554432: trees   = (const float*)p; break;
            case 780288:   indexes = (const int*)p;   break;
            case 98304:    if (!W1) W1 = (const float*)p; else W2 = (const float*)p; break;
            case 256:      b1 = (const float*)p; break;
            case 128:      b2 = (const float*)p; break;
            case 24576:    W3 = (const float*)p; break;
            case 64:       b3 = (const float*)p; break;
            case 2048:     W4 = (const float*)p; break;
            case 32:       if (!b4) b4 = (const float*)p; else W5 = (const float*)p; break;
            case 1:        b5 = (const float*)p; break;
            default: break;
        }
    }

    prep1<<<(128 * 3 * 256 + 255) / 256, 256>>>(W1);
    prep2<<<(256 * 3 * 128 + 255) / 256, 256>>>(W2);
    prep3<<<(128 * 3 * 64  + 255) / 256, 256>>>(W3);

    cudaFuncSetAttribute(bao_kernel, cudaFuncAttributeMaxDynamicSharedMemorySize, SMEM_BYTES);
    bao_kernel<<<2048, TPB, SMEM_BYTES>>>(trees, indexes, b1, b2, b3, W4, b4, W5, b5,
                                          (float*)d_out);
}